// round 16
// baseline (speedup 1.0000x reference)
#include <cuda_runtime.h>
#include <cstdint>

#define S_LEN 2048
#define BATCH 32
#define IDIM  256
#define HDIM  512
#define CL    8
#define THREADS_R 256

typedef unsigned long long ull;

__device__ __forceinline__ ull pack2(float x, float y) {
    ull r; asm("mov.b64 %0, {%1, %2};" : "=l"(r) : "f"(x), "f"(y)); return r;
}
__device__ __forceinline__ void unpack2(ull v, float &x, float &y) {
    asm("mov.b64 {%0, %1}, %2;" : "=f"(x), "=f"(y) : "l"(v));
}
__device__ __forceinline__ void ffma2(ull &d, ull a, ull b) {
    asm("fma.rn.f32x2 %0, %1, %2, %0;" : "+l"(d) : "l"(a), "l"(b));
}
__device__ __forceinline__ uint32_t smem_u32(const void* p) {
    return (uint32_t)__cvta_generic_to_shared(p);
}
__device__ __forceinline__ uint32_t mapa_addr(uint32_t laddr, uint32_t rank) {
    uint32_t raddr;
    asm("mapa.shared::cluster.u32 %0, %1, %2;" : "=r"(raddr) : "r"(laddr), "r"(rank));
    return raddr;
}
__device__ __forceinline__ void st_cluster_f32(uint32_t raddr, float v) {
    asm volatile("st.shared::cluster.b32 [%0], %1;"
                 :: "r"(raddr), "r"(__float_as_uint(v)) : "memory");
}
__device__ __forceinline__ void mbar_init(uint32_t mbar, uint32_t cnt) {
    asm volatile("mbarrier.init.shared.b64 [%0], %1;" :: "r"(mbar), "r"(cnt) : "memory");
}
__device__ __forceinline__ void mbar_arrive_cluster(uint32_t raddr) {
    asm volatile("mbarrier.arrive.release.cluster.shared::cluster.b64 _, [%0];"
                 :: "r"(raddr) : "memory");
}
__device__ __forceinline__ void mbar_wait_cl(uint32_t mbar, uint32_t parity) {
    uint32_t done;
    asm volatile("{\n\t.reg .pred p;\n\t"
                 "mbarrier.try_wait.parity.acquire.cluster.shared::cta.b64 p, [%1], %2;\n\t"
                 "selp.b32 %0, 1, 0, p;\n\t}"
                 : "=r"(done) : "r"(mbar), "r"(parity) : "memory");
    if (!done) {
        asm volatile("{\n\t.reg .pred P1;\n\t"
                     "WL%=:\n\t"
                     "mbarrier.try_wait.parity.acquire.cluster.shared::cta.b64 P1, [%0], %1, 0x989680;\n\t"
                     "@P1 bra.uni WD%=;\n\t"
                     "bra.uni WL%=;\n\t"
                     "WD%=:\n\t}"
                     :: "r"(mbar), "r"(parity) : "memory");
    }
}
__device__ __forceinline__ void cluster_sync_() {
    asm volatile("barrier.cluster.arrive.aligned;" ::: "memory");
    asm volatile("barrier.cluster.wait.aligned;"   ::: "memory");
}

// =====================================================================
// Phase 1: z = inputs @ Wih^T + (bih + bhh), in-place into d_out.
// =====================================================================
#define BM 64
#define BN 64
#define BK 32

__global__ __launch_bounds__(256) void zproj_kernel(
    const float* __restrict__ A, const float* __restrict__ W,
    const float* __restrict__ bih, const float* __restrict__ bhh,
    float* __restrict__ C)
{
    __shared__ __align__(16) float As[BK][BM + 8];
    __shared__ __align__(16) float Bs[BK][BN + 8];
    const int tid = threadIdx.x;
    const int m0 = blockIdx.x * BM;
    const int n0 = blockIdx.y * BN;
    const int tx = tid & 15;
    const int ty = tid >> 4;
    ull acc01[4] = {0,0,0,0};
    ull acc23[4] = {0,0,0,0};

    for (int k0 = 0; k0 < IDIM; k0 += BK) {
        #pragma unroll
        for (int i = 0; i < 2; i++) {
            int s  = tid + i * 256;
            int m  = s >> 3;
            int kq = (s & 7) << 2;
            float4 a = *(const float4*)(A + (size_t)(m0 + m) * IDIM + k0 + kq);
            As[kq+0][m] = a.x; As[kq+1][m] = a.y; As[kq+2][m] = a.z; As[kq+3][m] = a.w;
            float4 b = *(const float4*)(W + (size_t)(n0 + m) * IDIM + k0 + kq);
            Bs[kq+0][m] = b.x; Bs[kq+1][m] = b.y; Bs[kq+2][m] = b.z; Bs[kq+3][m] = b.w;
        }
        __syncthreads();
        #pragma unroll
        for (int k = 0; k < BK; k++) {
            float4 a4 = *(const float4*)&As[k][ty * 4];
            const ull* bp = (const ull*)&Bs[k][tx * 4];
            ull b01 = bp[0], b23 = bp[1];
            ull a0 = pack2(a4.x, a4.x);
            ull a1 = pack2(a4.y, a4.y);
            ull a2 = pack2(a4.z, a4.z);
            ull a3 = pack2(a4.w, a4.w);
            ffma2(acc01[0], a0, b01); ffma2(acc23[0], a0, b23);
            ffma2(acc01[1], a1, b01); ffma2(acc23[1], a1, b23);
            ffma2(acc01[2], a2, b01); ffma2(acc23[2], a2, b23);
            ffma2(acc01[3], a3, b01); ffma2(acc23[3], a3, b23);
        }
        __syncthreads();
    }

    float bias[4];
    #pragma unroll
    for (int j = 0; j < 4; j++)
        bias[j] = bih[n0 + tx * 4 + j] + bhh[n0 + tx * 4 + j];

    #pragma unroll
    for (int i = 0; i < 4; i++) {
        float4 o;
        unpack2(acc01[i], o.x, o.y);
        unpack2(acc23[i], o.z, o.w);
        o.x += bias[0]; o.y += bias[1]; o.z += bias[2]; o.w += bias[3];
        *(float4*)(C + (size_t)(m0 + ty * 4 + i) * HDIM + n0 + tx * 4) = o;
    }
}

// =====================================================================
// Phase 2: BATCH-PIPELINED cluster scan. hbuf[batch][buf][row] strides:
// batch = 4096B, buf = 2048B. mbarS[batch][buf][src]: (b*16+buf*8+src)*8.
// Batch b's DSMEM transit lands while the other batch's phase computes.
// =====================================================================
__global__ void __cluster_dims__(CL, 1, 1) __launch_bounds__(THREADS_R, 1)
rnn_scan_kernel(const float* __restrict__ Whh,
                const float* __restrict__ h0,
                float* __restrict__ out)
{
    __shared__ __align__(16) float hbuf[2][2][HDIM];  // [batch][buf][row]
    __shared__ __align__(16) float red[8][72];        // [chunk][row] (+pad)
    __shared__ __align__(8)  ull mbarS[2][2][CL];     // [batch][buf][src], cnt=1

    const int tid = threadIdx.x;
    const int w   = tid >> 5;            // warp = chunk = source rank consumed
    const int l   = tid & 31;
    uint32_t rank; asm("mov.u32 %0, %%cluster_ctarank;" : "=r"(rank));
    const int bb0 = (blockIdx.x / CL) * 2;

    const uint32_t mloc = smem_u32(&mbarS[0][0][0]);
    const uint32_t hloc = smem_u32(&hbuf[0][0][0]);

    // ---- W slice: rows {rank*64+2l, +1}, k in [64w, 64w+64) ----
    const int grow2 = (int)rank * 64 + 2 * l;
    const ull* wr0 = (const ull*)(Whh + (size_t)grow2 * HDIM + w * 64);
    const ull* wr1 = wr0 + (HDIM / 2);
    ull w2a[32], w2b[32];
    #pragma unroll
    for (int j = 0; j < 32; j++) { w2a[j] = wr0[j]; w2b[j] = wr1[j]; }

    // ---- init ----
    for (int g = tid; g < HDIM; g += THREADS_R) {
        hbuf[0][0][g] = h0[(size_t)bb0 * HDIM + g];
        hbuf[1][0][g] = h0[(size_t)(bb0 + 1) * HDIM + g];
    }
    if (tid < 4 * CL) mbar_init(mloc + tid * 8u, 1);
    __syncthreads();
    cluster_sync_();

    // ---- reducer identity: lanes l<8 of warp w own row rw = 8w+l ----
    const int rw   = 8 * w + (l & 7);
    const int grow = (int)rank * 64 + rw;
    const bool redu = (l < 8);
    size_t zoA = 0, zoB = 0, foA = 0, foB = 0;
    float zcA = 0.f, zcB = 0.f;
    if (redu) {
        zoA = ((size_t)bb0 * S_LEN) * HDIM + grow;
        zoB = ((size_t)(bb0 + 1) * S_LEN) * HDIM + grow;
        foA = (size_t)BATCH * S_LEN * HDIM + (size_t)bb0 * HDIM + grow;
        foB = foA + HDIM;
        zcA = out[zoA];
        zcB = out[zoB];
    }
    const uint32_t pbase = (uint32_t)grow * 4u;

    uint32_t arrB = 0;
    if (tid < CL) arrB = mapa_addr(mloc, (uint32_t)tid) + rank * 8u;
    const uint32_t wbase = mloc + (uint32_t)w * 8u;

    uint32_t p00 = 0, p01 = 0, p10 = 0, p11 = 0;

    for (int t = 0; t < S_LEN; t++) {
        const int cur = t & 1;
        const int nxt = cur ^ 1;
        const bool last = (t == S_LEN - 1);

        // ================= phase A (batch 0) =================
        {
            float znx = zcA;
            if (redu) znx = out[zoA + HDIM];
            if (t > 0) {
                if (cur) { mbar_wait_cl(wbase + 64u, p01); p01 ^= 1; }  // [0][1][w]
                else     { mbar_wait_cl(wbase,       p00); p00 ^= 1; }  // [0][0][w]
            }
            const ulonglong2* hb = (const ulonglong2*)&hbuf[0][cur][w * 64];
            ull a0 = 0, a1 = 0;
            #pragma unroll
            for (int j2 = 0; j2 < 16; j2++) {
                ulonglong2 u = hb[j2];
                ffma2(a0, w2a[2*j2],   u.x);
                ffma2(a1, w2b[2*j2],   u.x);
                ffma2(a0, w2a[2*j2+1], u.y);
                ffma2(a1, w2b[2*j2+1], u.y);
            }
            float x, y, s0, s1;
            unpack2(a0, x, y); s0 = x + y;
            unpack2(a1, x, y); s1 = x + y;
            *(float2*)&red[w][2*l] = make_float2(s0, s1);
            __syncthreads();
            if (redu) {
                float s = zcA;
                #pragma unroll
                for (int q = 0; q < 8; q++) s += red[q][rw];
                float v = fmaxf(s, 0.f);
                out[zoA] = v;
                if (last) out[foA] = v;
                else {
                    const uint32_t off = (uint32_t)nxt * 2048u + pbase;      // hbuf[0][nxt]
                    #pragma unroll
                    for (uint32_t r = 0; r < CL; r++)
                        st_cluster_f32(mapa_addr(hloc + off, r), v);
                }
                zcA = znx;
                zoA += HDIM;
            }
            __syncthreads();
            if (tid < CL && !last)
                mbar_arrive_cluster(arrB + (uint32_t)nxt * 64u);             // [0][nxt][rank]
        }

        // ================= phase B (batch 1) =================
        {
            float znx = zcB;
            if (redu) znx = out[zoB + HDIM];
            if (t > 0) {
                if (cur) { mbar_wait_cl(wbase + 192u, p11); p11 ^= 1; }  // [1][1][w]
                else     { mbar_wait_cl(wbase + 128u, p10); p10 ^= 1; }  // [1][0][w]
            }
            const ulonglong2* hb = (const ulonglong2*)&hbuf[1][cur][w * 64];
            ull a0 = 0, a1 = 0;
            #pragma unroll
            for (int j2 = 0; j2 < 16; j2++) {
                ulonglong2 u = hb[j2];
                ffma2(a0, w2a[2*j2],   u.x);
                ffma2(a1, w2b[2*j2],   u.x);
                ffma2(a0, w2a[2*j2+1], u.y);
                ffma2(a1, w2b[2*j2+1], u.y);
            }
            float x, y, s0, s1;
            unpack2(a0, x, y); s0 = x + y;
            unpack2(a1, x, y); s1 = x + y;
            *(float2*)&red[w][2*l] = make_float2(s0, s1);
            __syncthreads();
            if (redu) {
                float s = zcB;
                #pragma unroll
                for (int q = 0; q < 8; q++) s += red[q][rw];
                float v = fmaxf(s, 0.f);
                out[zoB] = v;
                if (last) out[foB] = v;
                else {
                    // FIX: batch stride is 4096B (was 8192B -> OOB smem stomp)
                    const uint32_t off = 4096u + (uint32_t)nxt * 2048u + pbase;  // hbuf[1][nxt]
                    #pragma unroll
                    for (uint32_t r = 0; r < CL; r++)
                        st_cluster_f32(mapa_addr(hloc + off, r), v);
                }
                zcB = znx;
                zoB += HDIM;
            }
            __syncthreads();
            if (tid < CL && !last)
                mbar_arrive_cluster(arrB + 128u + (uint32_t)nxt * 64u);          // [1][nxt][rank]
        }
    }
    cluster_sync_();
}

// =====================================================================
extern "C" void kernel_launch(void* const* d_in, const int* in_sizes, int n_in,
                              void* d_out, int out_size) {
    (void)in_sizes; (void)n_in; (void)out_size;
    const float* inputs = (const float*)d_in[0];
    const float* h0     = (const float*)d_in[1];
    const float* Wih    = (const float*)d_in[2];
    const float* Whh    = (const float*)d_in[3];
    const float* bih    = (const float*)d_in[4];
    const float* bhh    = (const float*)d_in[5];
    float* out = (float*)d_out;

    dim3 g1((BATCH * S_LEN) / BM, HDIM / BN);
    zproj_kernel<<<g1, 256>>>(inputs, Wih, bih, bhh, out);
    rnn_scan_kernel<<<(BATCH / 2) * CL, THREADS_R>>>(Whh, h0, out);
}

// round 17
// speedup vs baseline: 1.3525x; 1.3525x over previous
#include <cuda_runtime.h>
#include <cstdint>

#define S_LEN 2048
#define BATCH 32
#define IDIM  256
#define HDIM  512
#define CL    8
#define THREADS_R 256

typedef unsigned long long ull;

__device__ __forceinline__ ull pack2(float x, float y) {
    ull r; asm("mov.b64 %0, {%1, %2};" : "=l"(r) : "f"(x), "f"(y)); return r;
}
__device__ __forceinline__ void unpack2(ull v, float &x, float &y) {
    asm("mov.b64 {%0, %1}, %2;" : "=f"(x), "=f"(y) : "l"(v));
}
__device__ __forceinline__ void ffma2(ull &d, ull a, ull b) {
    asm("fma.rn.f32x2 %0, %1, %2, %0;" : "+l"(d) : "l"(a), "l"(b));
}
__device__ __forceinline__ uint32_t smem_u32(const void* p) {
    return (uint32_t)__cvta_generic_to_shared(p);
}
__device__ __forceinline__ uint32_t mapa_addr(uint32_t laddr, uint32_t rank) {
    uint32_t raddr;
    asm("mapa.shared::cluster.u32 %0, %1, %2;" : "=r"(raddr) : "r"(laddr), "r"(rank));
    return raddr;
}
__device__ __forceinline__ void st_cluster_u64(uint32_t raddr, ull v) {
    asm volatile("st.shared::cluster.b64 [%0], %1;"
                 :: "r"(raddr), "l"(v) : "memory");
}
__device__ __forceinline__ void mbar_init(uint32_t mbar, uint32_t cnt) {
    asm volatile("mbarrier.init.shared.b64 [%0], %1;" :: "r"(mbar), "r"(cnt) : "memory");
}
__device__ __forceinline__ void mbar_arrive_cluster(uint32_t raddr) {
    asm volatile("mbarrier.arrive.release.cluster.shared::cluster.b64 _, [%0];"
                 :: "r"(raddr) : "memory");
}
__device__ __forceinline__ void mbar_wait_cl(uint32_t mbar, uint32_t parity) {
    uint32_t done;
    asm volatile("{\n\t.reg .pred p;\n\t"
                 "mbarrier.try_wait.parity.acquire.cluster.shared::cta.b64 p, [%1], %2;\n\t"
                 "selp.b32 %0, 1, 0, p;\n\t}"
                 : "=r"(done) : "r"(mbar), "r"(parity) : "memory");
    if (!done) {
        asm volatile("{\n\t.reg .pred P1;\n\t"
                     "WL%=:\n\t"
                     "mbarrier.try_wait.parity.acquire.cluster.shared::cta.b64 P1, [%0], %1, 0x989680;\n\t"
                     "@P1 bra.uni WD%=;\n\t"
                     "bra.uni WL%=;\n\t"
                     "WD%=:\n\t}"
                     :: "r"(mbar), "r"(parity) : "memory");
    }
}
__device__ __forceinline__ void cluster_sync_() {
    asm volatile("barrier.cluster.arrive.aligned;" ::: "memory");
    asm volatile("barrier.cluster.wait.aligned;"   ::: "memory");
}

// =====================================================================
// Phase 1: z = inputs @ Wih^T + (bih + bhh), in-place into d_out.
// (unchanged — best passing version)
// =====================================================================
#define BM 64
#define BN 64
#define BK 32

__global__ __launch_bounds__(256) void zproj_kernel(
    const float* __restrict__ A, const float* __restrict__ W,
    const float* __restrict__ bih, const float* __restrict__ bhh,
    float* __restrict__ C)
{
    __shared__ __align__(16) float As[BK][BM + 8];
    __shared__ __align__(16) float Bs[BK][BN + 8];
    const int tid = threadIdx.x;
    const int m0 = blockIdx.x * BM;
    const int n0 = blockIdx.y * BN;
    const int tx = tid & 15;
    const int ty = tid >> 4;
    ull acc01[4] = {0,0,0,0};
    ull acc23[4] = {0,0,0,0};

    for (int k0 = 0; k0 < IDIM; k0 += BK) {
        #pragma unroll
        for (int i = 0; i < 2; i++) {
            int s  = tid + i * 256;
            int m  = s >> 3;
            int kq = (s & 7) << 2;
            float4 a = *(const float4*)(A + (size_t)(m0 + m) * IDIM + k0 + kq);
            As[kq+0][m] = a.x; As[kq+1][m] = a.y; As[kq+2][m] = a.z; As[kq+3][m] = a.w;
            float4 b = *(const float4*)(W + (size_t)(n0 + m) * IDIM + k0 + kq);
            Bs[kq+0][m] = b.x; Bs[kq+1][m] = b.y; Bs[kq+2][m] = b.z; Bs[kq+3][m] = b.w;
        }
        __syncthreads();
        #pragma unroll
        for (int k = 0; k < BK; k++) {
            float4 a4 = *(const float4*)&As[k][ty * 4];
            const ull* bp = (const ull*)&Bs[k][tx * 4];
            ull b01 = bp[0], b23 = bp[1];
            ull a0 = pack2(a4.x, a4.x);
            ull a1 = pack2(a4.y, a4.y);
            ull a2 = pack2(a4.z, a4.z);
            ull a3 = pack2(a4.w, a4.w);
            ffma2(acc01[0], a0, b01); ffma2(acc23[0], a0, b23);
            ffma2(acc01[1], a1, b01); ffma2(acc23[1], a1, b23);
            ffma2(acc01[2], a2, b01); ffma2(acc23[2], a2, b23);
            ffma2(acc01[3], a3, b01); ffma2(acc23[3], a3, b23);
        }
        __syncthreads();
    }

    float bias[4];
    #pragma unroll
    for (int j = 0; j < 4; j++)
        bias[j] = bih[n0 + tx * 4 + j] + bhh[n0 + tx * 4 + j];

    #pragma unroll
    for (int i = 0; i < 4; i++) {
        float4 o;
        unpack2(acc01[i], o.x, o.y);
        unpack2(acc23[i], o.z, o.w);
        o.x += bias[0]; o.y += bias[1]; o.z += bias[2]; o.w += bias[3];
        *(float4*)(C + (size_t)(m0 + ty * 4 + i) * HDIM + n0 + tx * 4) = o;
    }
}

// =====================================================================
// Phase 2: R11 structure + deep z prefetch (t+2), 8B pushes by 64
// reducers, named-bar(64) before an early release-arrive, red double-
// buffered so warps 2-7 decouple straight into the next wait.
// hbuf[buf][batch][row]: buf stride 4096B, batch 2048B.
// mbarS[buf][src]: (buf*8+src)*8 bytes. 1 arrival per barrier per step.
// =====================================================================
__global__ void __cluster_dims__(CL, 1, 1) __launch_bounds__(THREADS_R, 1)
rnn_scan_kernel(const float* __restrict__ Whh,
                const float* __restrict__ h0,
                float* __restrict__ out)
{
    __shared__ __align__(16) float hbuf[2][2][HDIM];   // [buf][batch][row]
    __shared__ __align__(16) float red[2][8][132];     // [phase][chunk][pb*64+row] (+pad)
    __shared__ __align__(8)  ull mbarS[2][CL];         // [buf][src], cnt=1

    const int tid = threadIdx.x;
    const int w   = tid >> 5;            // warp = k-chunk = source rank consumed
    const int l   = tid & 31;
    uint32_t rank; asm("mov.u32 %0, %%cluster_ctarank;" : "=r"(rank));
    const int bb0 = (blockIdx.x / CL) * 2;

    const uint32_t mloc = smem_u32(&mbarS[0][0]);
    const uint32_t hloc = smem_u32(&hbuf[0][0][0]);

    // ---- W slice: rows {rank*64+2l, +1}, k in [64w, 64w+64) ----
    const int grow2 = (int)rank * 64 + 2 * l;
    const ull* wr0 = (const ull*)(Whh + (size_t)grow2 * HDIM + w * 64);
    const ull* wr1 = wr0 + (HDIM / 2);
    ull w2a[32], w2b[32];
    #pragma unroll
    for (int j = 0; j < 32; j++) { w2a[j] = wr0[j]; w2b[j] = wr1[j]; }

    // ---- init: h0 both batches into buf 0; barriers ----
    for (int g = tid; g < HDIM; g += THREADS_R) {
        hbuf[0][0][g] = h0[(size_t)bb0 * HDIM + g];
        hbuf[0][1][g] = h0[(size_t)(bb0 + 1) * HDIM + g];
    }
    if (tid < 2 * CL) mbar_init(mloc + tid * 8u, 1);
    __syncthreads();
    cluster_sync_();

    // ---- reducer identity: tid<64 -> batch pb = tid>>5, rowpair rp = tid&31 ----
    const bool redu = (tid < 64);
    const int  pb   = tid >> 5;
    const int  rp   = tid & 31;
    const int  growp = (int)rank * 64 + 2 * rp;       // first row of the pair
    size_t zoff = 0, foff = 0;
    float2 z_cur = make_float2(0.f, 0.f), z_nx1 = z_cur;
    uint32_t rbh[CL];
    if (redu) {
        zoff = ((size_t)(bb0 + pb) * S_LEN) * HDIM + growp;
        foff = (size_t)BATCH * S_LEN * HDIM + (size_t)(bb0 + pb) * HDIM + growp;
        z_cur = *(const float2*)(out + zoff);          // z[0]
        z_nx1 = *(const float2*)(out + zoff + HDIM);   // z[1]
        #pragma unroll
        for (uint32_t r = 0; r < CL; r++) rbh[r] = mapa_addr(hloc, r);
    }
    const uint32_t pushb = (uint32_t)(pb * HDIM + growp) * 4u;  // byte off within buf

    uint32_t arrA = 0;
    if (tid < CL) arrA = mapa_addr(mloc, (uint32_t)tid) + rank * 8u;
    const uint32_t wbase = mloc + (uint32_t)w * 8u;

    uint32_t p0 = 0, p1 = 0;
    for (int t = 0; t < S_LEN; t++) {
        const int cur = t & 1;
        const int nxt = cur ^ 1;
        const bool last = (t == S_LEN - 1);

        // deep prefetch: z[t+2] (t+2 <= S_LEN+1 stays inside d_out incl. tail)
        float2 z_nx2 = z_nx1;
        if (redu) z_nx2 = *(const float2*)(out + zoff + 2 * HDIM);

        if (t > 0) {   // warp w waits only for source CTA w's slice of buf[cur]
            if (cur) { mbar_wait_cl(wbase + 64u, p1); p1 ^= 1; }   // [1][w]
            else     { mbar_wait_cl(wbase,       p0); p0 ^= 1; }   // [0][w]
        }

        // ---- matvec: rows {2l,2l+1}, chunk w, both batches, local LDS ----
        const ulonglong2* hb0 = (const ulonglong2*)&hbuf[cur][0][w * 64];
        const ulonglong2* hb1 = (const ulonglong2*)&hbuf[cur][1][w * 64];
        ull aA0 = 0, aA1 = 0, aB0 = 0, aB1 = 0;
        #pragma unroll
        for (int j2 = 0; j2 < 16; j2++) {
            ulonglong2 u0 = hb0[j2];
            ulonglong2 u1 = hb1[j2];
            ffma2(aA0, w2a[2*j2],   u0.x);
            ffma2(aA1, w2b[2*j2],   u0.x);
            ffma2(aB0, w2a[2*j2],   u1.x);
            ffma2(aB1, w2b[2*j2],   u1.x);
            ffma2(aA0, w2a[2*j2+1], u0.y);
            ffma2(aA1, w2b[2*j2+1], u0.y);
            ffma2(aB0, w2a[2*j2+1], u1.y);
            ffma2(aB1, w2b[2*j2+1], u1.y);
        }
        float x, y, pA0, pA1, pB0, pB1;
        unpack2(aA0, x, y); pA0 = x + y;
        unpack2(aA1, x, y); pA1 = x + y;
        unpack2(aB0, x, y); pB0 = x + y;
        unpack2(aB1, x, y); pB1 = x + y;

        *(float2*)&red[cur][w][2*l]      = make_float2(pA0, pA1);  // batch0
        *(float2*)&red[cur][w][64 + 2*l] = make_float2(pB0, pB1);  // batch1
        __syncthreads();

        if (redu) {
            float s0 = z_cur.x, s1 = z_cur.y;
            #pragma unroll
            for (int q = 0; q < 8; q++) {
                float2 r2 = *(const float2*)&red[cur][q][pb * 64 + 2 * rp];
                s0 += r2.x; s1 += r2.y;
            }
            float v0 = fmaxf(s0, 0.f);
            float v1 = fmaxf(s1, 0.f);
            if (!last) {
                ull pv = pack2(v0, v1);
                const uint32_t off = (uint32_t)nxt * 4096u + pushb;
                #pragma unroll
                for (uint32_t r = 0; r < CL; r++)
                    st_cluster_u64(rbh[r] + off, pv);
            }
            asm volatile("bar.sync 1, 64;" ::: "memory");   // warps 0-1 pushes done
            if (tid < CL && !last)
                mbar_arrive_cluster(arrA + (uint32_t)nxt * 64u);   // [nxt][rank] at rank tid
            // off critical path: global h store + z rotation
            *(float2*)(out + zoff) = make_float2(v0, v1);
            if (last) *(float2*)(out + foff) = make_float2(v0, v1);
            z_cur = z_nx1;
            z_nx1 = z_nx2;
            zoff += HDIM;
        }
        // warps 2-7 fall through to the next wait (red double-buffered)
    }
    cluster_sync_();
}

// =====================================================================
extern "C" void kernel_launch(void* const* d_in, const int* in_sizes, int n_in,
                              void* d_out, int out_size) {
    (void)in_sizes; (void)n_in; (void)out_size;
    const float* inputs = (const float*)d_in[0];
    const float* h0     = (const float*)d_in[1];
    const float* Wih    = (const float*)d_in[2];
    const float* Whh    = (const float*)d_in[3];
    const float* bih    = (const float*)d_in[4];
    const float* bhh    = (const float*)d_in[5];
    float* out = (float*)d_out;

    dim3 g1((BATCH * S_LEN) / BM, HDIM / BN);
    zproj_kernel<<<g1, 256>>>(inputs, Wih, bih, bhh, out);
    rnn_scan_kernel<<<(BATCH / 2) * CL, THREADS_R>>>(Whh, h0, out);
}